// round 8
// baseline (speedup 1.0000x reference)
#include <cuda_runtime.h>
#include <stdint.h>

// Problem constants
#define B_  8
#define L_  4096
#define D_  1024
#define H_  16
#define DH_ 64
#define FF_ 4

constexpr int    M_ROWS = B_ * L_;                 // 32768
constexpr size_t BLD    = (size_t)M_ROWS * D_;     // 33,554,432 floats

// -------- scratch (static device globals; no allocations allowed) --------
__device__ float g_Xp  [BLD];                      // X + pe (fp32, residual)
__device__ float g_XpR [BLD];                      // X + pe (tf32-rounded, GEMM A)
__device__ float g_q   [BLD];
__device__ float g_k   [BLD];
__device__ float g_v   [BLD];
__device__ float g_ctx [BLD];                      // attention out (tf32-rounded)
__device__ float g_t1  [BLD];
__device__ float g_X1  [BLD];                      // LN1 out fp32 (residual)
__device__ float g_X1R [BLD];                      // LN1 out tf32-rounded (GEMM A)
__device__ float g_hid [BLD * FF_];                // FFN hidden (tf32-rounded)
// packed transposed+rounded QKV weights: rows 0-1023 Wq^T, 1024-2047 Wk^T, 2048-3071 Wv^T
__device__ float g_Wqkv[(size_t)3 * D_ * D_];
__device__ float g_bqkv[3 * D_];
__device__ float g_WoT [D_ * D_];
__device__ float g_W1T [(size_t)D_ * FF_ * D_];
__device__ float g_W2T [(size_t)FF_ * D_ * D_];

// round fp32 -> tf32 (round-half-up at bit 13); idempotent
__device__ __forceinline__ float f2tf32f(float x) {
    uint32_t u = (__float_as_uint(x) + 0x1000u) & 0xFFFFE000u;
    return __uint_as_float(u);
}

__device__ __forceinline__ void mma_tf32(float* c, const uint32_t* a,
                                         uint32_t b0, uint32_t b1) {
    asm volatile(
        "mma.sync.aligned.m16n8k8.row.col.f32.tf32.tf32.f32 "
        "{%0,%1,%2,%3}, {%4,%5,%6,%7}, {%8,%9}, {%0,%1,%2,%3};\n"
        : "+f"(c[0]), "+f"(c[1]), "+f"(c[2]), "+f"(c[3])
        : "r"(a[0]), "r"(a[1]), "r"(a[2]), "r"(a[3]), "r"(b0), "r"(b1));
}

// =====================================================================
// tf32 mma.sync GEMM, double-buffered static smem (LDG->reg->STS).
// C = A[M,K] @ Bt[N,K]^T + bias; optional ReLU / tf32-round of output.
// SPLIT3: N covers 3 packed outputs; each 128-wide CTA stripe is routed
// to C0/C1/C2 with column offset (stride N/3). bias indexed by packed col.
// CTA tile 128x128, BK=16, 256 threads (8 warps, 4x2), warp tile 32x64.
// SMEM tiles [row][k], pitch 20 floats -> conflict-free fragment loads.
// Inputs must already be tf32-rounded (loader copies raw bits).
// =====================================================================
constexpr int PITCH  = 20;                 // floats per tile row
constexpr int TILE_F = 128 * PITCH;        // 2560 floats per tile

template<bool RELU, bool ROUND, bool SPLIT3>
__global__ __launch_bounds__(256)
void k_mmagemm(const float* __restrict__ A, const float* __restrict__ Bt,
               const float* __restrict__ bias,
               float* __restrict__ C0, float* __restrict__ C1,
               float* __restrict__ C2,
               int M, int N, int K) {
    __shared__ float sm[2][2 * TILE_F];    // [buf][A tile | B tile] = 40960 B

    const int tid  = threadIdx.x;
    const int wid  = tid >> 5;
    const int lane = tid & 31;
    const int ar   = lane >> 2;            // 0..7
    const int ac   = lane & 3;             // 0..3
    const int wm   = (wid & 3) * 32;
    const int wn   = (wid >> 2) * 64;

    const int m0 = blockIdx.y * 128;
    const int n0 = blockIdx.x * 128;
    const float* Ag = A  + (size_t)m0 * K;
    const float* Bg = Bt + (size_t)n0 * K;

    // loader mapping: 2 float4 per operand tile per thread per stage
    const int row0 = tid >> 2,          c40 = tid & 3;
    const int row1 = (tid + 256) >> 2,  c41 = tid & 3;

    float c[2][8][4];
    #pragma unroll
    for (int mt = 0; mt < 2; mt++)
        #pragma unroll
        for (int nt = 0; nt < 8; nt++)
            #pragma unroll
            for (int i = 0; i < 4; i++) c[mt][nt][i] = 0.f;

    // ---- prologue: stage 0 -> buf 0
    {
        float4 a0 = *(const float4*)(Ag + (size_t)row0 * K + c40 * 4);
        float4 a1 = *(const float4*)(Ag + (size_t)row1 * K + c41 * 4);
        float4 b0 = *(const float4*)(Bg + (size_t)row0 * K + c40 * 4);
        float4 b1 = *(const float4*)(Bg + (size_t)row1 * K + c41 * 4);
        *(float4*)(&sm[0][row0 * PITCH + c40 * 4])          = a0;
        *(float4*)(&sm[0][row1 * PITCH + c41 * 4])          = a1;
        *(float4*)(&sm[0][TILE_F + row0 * PITCH + c40 * 4]) = b0;
        *(float4*)(&sm[0][TILE_F + row1 * PITCH + c41 * 4]) = b1;
    }
    __syncthreads();

    const int nStages = K >> 4;
    int buf = 0;
    for (int s = 0; s < nStages; s++) {
        const bool has_next = (s + 1 < nStages);
        float4 a0, a1, b0v, b1v;
        if (has_next) {
            const int kb = (s + 1) << 4;
            a0  = *(const float4*)(Ag + (size_t)row0 * K + kb + c40 * 4);
            a1  = *(const float4*)(Ag + (size_t)row1 * K + kb + c41 * 4);
            b0v = *(const float4*)(Bg + (size_t)row0 * K + kb + c40 * 4);
            b1v = *(const float4*)(Bg + (size_t)row1 * K + kb + c41 * 4);
        }

        const float* As = sm[buf];
        const float* Bs = sm[buf] + TILE_F;
        #pragma unroll
        for (int kk = 0; kk < 2; kk++) {
            const int k0 = kk * 8;
            uint32_t afr[2][4];
            #pragma unroll
            for (int mt = 0; mt < 2; mt++) {
                const int mb = wm + mt * 16 + ar;
                afr[mt][0] = __float_as_uint(As[mb * PITCH + k0 + ac]);
                afr[mt][1] = __float_as_uint(As[(mb + 8) * PITCH + k0 + ac]);
                afr[mt][2] = __float_as_uint(As[mb * PITCH + k0 + ac + 4]);
                afr[mt][3] = __float_as_uint(As[(mb + 8) * PITCH + k0 + ac + 4]);
            }
            #pragma unroll
            for (int nt = 0; nt < 8; nt++) {
                const int nb = wn + nt * 8 + ar;
                const uint32_t bb0 = __float_as_uint(Bs[nb * PITCH + k0 + ac]);
                const uint32_t bb1 = __float_as_uint(Bs[nb * PITCH + k0 + ac + 4]);
                mma_tf32(c[0][nt], afr[0], bb0, bb1);
                mma_tf32(c[1][nt], afr[1], bb0, bb1);
            }
        }

        if (has_next) {
            const int nb2 = buf ^ 1;
            *(float4*)(&sm[nb2][row0 * PITCH + c40 * 4])          = a0;
            *(float4*)(&sm[nb2][row1 * PITCH + c41 * 4])          = a1;
            *(float4*)(&sm[nb2][TILE_F + row0 * PITCH + c40 * 4]) = b0v;
            *(float4*)(&sm[nb2][TILE_F + row1 * PITCH + c41 * 4]) = b1v;
            __syncthreads();
            buf = nb2;
        }
    }

    // ---- epilogue: route output (SPLIT3), bias (+ReLU) (+round), float2 stores
    float* Cout = C0;
    int    ncol0 = n0;
    int    Nout  = N;
    if (SPLIT3) {
        Nout = N / 3;
        if (n0 >= 2 * Nout)      { Cout = C2; ncol0 = n0 - 2 * Nout; }
        else if (n0 >= Nout)     { Cout = C1; ncol0 = n0 - Nout; }
    }

    #pragma unroll
    for (int nt = 0; nt < 8; nt++) {
        const int coff = wn + nt * 8 + 2 * ac;
        const float2 bb = *(const float2*)(bias + n0 + coff);
        #pragma unroll
        for (int mt = 0; mt < 2; mt++) {
            const int r0 = m0 + wm + mt * 16 + ar;
            float2 o0 = { c[mt][nt][0] + bb.x, c[mt][nt][1] + bb.y };
            float2 o1 = { c[mt][nt][2] + bb.x, c[mt][nt][3] + bb.y };
            if (RELU) {
                o0.x = fmaxf(o0.x, 0.f); o0.y = fmaxf(o0.y, 0.f);
                o1.x = fmaxf(o1.x, 0.f); o1.y = fmaxf(o1.y, 0.f);
            }
            if (ROUND) {
                o0.x = f2tf32f(o0.x); o0.y = f2tf32f(o0.y);
                o1.x = f2tf32f(o1.x); o1.y = f2tf32f(o1.y);
            }
            *(float2*)(Cout + (size_t)r0 * Nout + ncol0 + coff)       = o0;
            *(float2*)(Cout + (size_t)(r0 + 8) * Nout + ncol0 + coff) = o1;
        }
    }
}

// =====================================================================
// weight transpose + tf32 round: Wt[n][k] = round(W[k][n]).
// Optionally packs bias (bias_dst[n] = bias_src[n]) from blocks with
// blockIdx.y == 0.
// =====================================================================
__global__ void k_transpose(const float* __restrict__ W, float* __restrict__ Wt,
                            int K, int N,
                            const float* __restrict__ bias_src,
                            float* __restrict__ bias_dst) {
    __shared__ float t[32][33];
    const int n0 = blockIdx.x * 32, k0 = blockIdx.y * 32;
    const int tx = threadIdx.x, ty = threadIdx.y;       // (32, 8)
    #pragma unroll
    for (int j = 0; j < 32; j += 8)
        t[ty + j][tx] = W[(size_t)(k0 + ty + j) * N + n0 + tx];
    __syncthreads();
    #pragma unroll
    for (int j = 0; j < 32; j += 8)
        Wt[(size_t)(n0 + ty + j) * K + k0 + tx] = f2tf32f(t[tx][ty + j]);
    if (bias_dst != nullptr && blockIdx.y == 0 && ty == 0)
        bias_dst[n0 + tx] = bias_src[n0 + tx];
}

// =====================================================================
// X + pe -> Xp (fp32) and XpR (tf32-rounded)
// =====================================================================
__global__ void k_add_pe(const float* __restrict__ X,
                         const float* __restrict__ pe,
                         float* __restrict__ outF,
                         float* __restrict__ outR) {
    size_t i = (size_t)blockIdx.x * blockDim.x + threadIdx.x;
    const size_t n4  = BLD / 4;
    const size_t ld4 = (size_t)L_ * D_ / 4;
    if (i >= n4) return;
    const float4 a = ((const float4*)X)[i];
    const float4 p = ((const float4*)pe)[i % ld4];
    float4 o;
    o.x = a.x + p.x; o.y = a.y + p.y; o.z = a.z + p.z; o.w = a.w + p.w;
    ((float4*)outF)[i] = o;
    float4 r = { f2tf32f(o.x), f2tf32f(o.y), f2tf32f(o.z), f2tf32f(o.w) };
    ((float4*)outR)[i] = r;
}

// =====================================================================
// windowed attention (window 3), one warp per (b,l,h); tf32-rounded out
// =====================================================================
__global__ void k_attn(const float* __restrict__ q, const float* __restrict__ k,
                       const float* __restrict__ v,
                       const uint8_t* __restrict__ mask,
                       float* __restrict__ ctx) {
    const int gw   = (int)(((size_t)blockIdx.x * blockDim.x + threadIdx.x) >> 5);
    const int lane = threadIdx.x & 31;
    if (gw >= B_ * L_ * H_) return;
    const int h  = gw % H_;
    const int bl = gw / H_;
    const int l  = bl % L_;
    const int b  = bl / L_;

    const float* qp = q + (size_t)bl * D_ + h * DH_;
    const float  q0 = qp[lane];
    const float  q1 = qp[lane + 32];

    float s[3], v0[3], v1[3];
    bool  allow[3];
    #pragma unroll
    for (int w = 0; w < 3; w++) {
        const int j     = l + w - 1;
        const bool vald = (j >= 0) && (j < L_);
        const int jc    = min(max(j, 0), L_ - 1);
        const size_t kr = ((size_t)b * L_ + jc) * D_ + h * DH_;
        float p = q0 * k[kr + lane] + q1 * k[kr + lane + 32];
        #pragma unroll
        for (int o = 16; o > 0; o >>= 1) p += __shfl_xor_sync(0xffffffffu, p, o);
        s[w]     = p * 0.125f;
        allow[w] = vald && (mask[(size_t)b * L_ + jc] == 0);
        v0[w]    = v[kr + lane];
        v1[w]    = v[kr + lane + 32];
    }

    float sw[3], m = -1e30f;
    #pragma unroll
    for (int w = 0; w < 3; w++) { sw[w] = allow[w] ? s[w] : -1e30f; m = fmaxf(m, sw[w]); }
    float e[3], sum = 0.f;
    #pragma unroll
    for (int w = 0; w < 3; w++) { e[w] = expf(sw[w] - m); sum += e[w]; }
    const float inv = 1.f / sum;
    float o0 = 0.f, o1 = 0.f;
    #pragma unroll
    for (int w = 0; w < 3; w++) {
        const float a = e[w] * inv;
        o0 = fmaf(a, v0[w], o0);
        o1 = fmaf(a, v1[w], o1);
    }
    float* cp = ctx + (size_t)bl * D_ + h * DH_;
    cp[lane]      = f2tf32f(o0);
    cp[lane + 32] = f2tf32f(o1);
}

// =====================================================================
// out = layernorm(A + R) * g + beta ; optional rounded second output
// =====================================================================
__device__ __forceinline__ float block_sum(float val, float* sbuf) {
    const int lane = threadIdx.x & 31, wid = threadIdx.x >> 5;
    #pragma unroll
    for (int o = 16; o > 0; o >>= 1) val += __shfl_xor_sync(0xffffffffu, val, o);
    if (lane == 0) sbuf[wid] = val;
    __syncthreads();
    if (wid == 0) {
        float vv = (lane < 8) ? sbuf[lane] : 0.f;
        #pragma unroll
        for (int o = 4; o > 0; o >>= 1) vv += __shfl_xor_sync(0xffffffffu, vv, o);
        if (lane == 0) sbuf[0] = vv;
    }
    __syncthreads();
    const float r = sbuf[0];
    __syncthreads();
    return r;
}

template<bool DUAL>
__global__ __launch_bounds__(256)
void k_add_ln(const float* __restrict__ A, const float* __restrict__ R,
              const float* __restrict__ g, const float* __restrict__ beta,
              float* __restrict__ out, float* __restrict__ outR) {
    __shared__ float sbuf[8];
    const int row = blockIdx.x;
    const int tid = threadIdx.x;
    const size_t base = (size_t)row * D_;

    const float4 a = ((const float4*)(A + base))[tid];
    const float4 r = ((const float4*)(R + base))[tid];
    float x[4] = { a.x + r.x, a.y + r.y, a.z + r.z, a.w + r.w };

    float ps = x[0] + x[1] + x[2] + x[3];
    const float mean = block_sum(ps, sbuf) * (1.f / D_);

    float pv = 0.f;
    #pragma unroll
    for (int i = 0; i < 4; i++) { const float d = x[i] - mean; pv += d * d; }
    const float var = block_sum(pv, sbuf) * (1.f / D_);
    const float rstd = rsqrtf(var + 1e-5f);

    const float4 gg = ((const float4*)g)[tid];
    const float4 bb = ((const float4*)beta)[tid];
    float4 o;
    o.x = (x[0] - mean) * rstd * gg.x + bb.x;
    o.y = (x[1] - mean) * rstd * gg.y + bb.y;
    o.z = (x[2] - mean) * rstd * gg.z + bb.z;
    o.w = (x[3] - mean) * rstd * gg.w + bb.w;
    ((float4*)(out + base))[tid] = o;
    if (DUAL) {
        float4 rr = { f2tf32f(o.x), f2tf32f(o.y), f2tf32f(o.z), f2tf32f(o.w) };
        ((float4*)(outR + base))[tid] = rr;
    }
}

// =====================================================================
// launch
// (order chosen so launch index 5 — the one ncu captures — is the big
//  fused QKV GEMM, not a transpose)
// =====================================================================
extern "C" void kernel_launch(void* const* d_in, const int* in_sizes, int n_in,
                              void* d_out, int out_size) {
    const float*   X    = (const float*)d_in[0];
    const uint8_t* mask = (const uint8_t*)d_in[1];
    const float*   pe   = (const float*)d_in[2];
    const float*   Wq   = (const float*)d_in[3];
    const float*   Wk   = (const float*)d_in[4];
    const float*   Wv   = (const float*)d_in[5];
    const float*   bq   = (const float*)d_in[6];
    const float*   bk   = (const float*)d_in[7];
    const float*   bv   = (const float*)d_in[8];
    const float*   Wo   = (const float*)d_in[9];
    const float*   bo   = (const float*)d_in[10];
    const float*   g1   = (const float*)d_in[11];
    const float*   be1  = (const float*)d_in[12];
    const float*   W1   = (const float*)d_in[13];
    const float*   b1   = (const float*)d_in[14];
    const float*   W2   = (const float*)d_in[15];
    const float*   b2   = (const float*)d_in[16];
    const float*   g2   = (const float*)d_in[17];
    const float*   be2  = (const float*)d_in[18];
    float*         out  = (float*)d_out;

    float *Xp, *XpR, *q, *k, *v, *ctx, *t1, *X1, *X1R, *hid;
    float *Wqkv, *bqkv, *WoT, *W1T, *W2T;
    cudaGetSymbolAddress((void**)&Xp,   g_Xp);
    cudaGetSymbolAddress((void**)&XpR,  g_XpR);
    cudaGetSymbolAddress((void**)&q,    g_q);
    cudaGetSymbolAddress((void**)&k,    g_k);
    cudaGetSymbolAddress((void**)&v,    g_v);
    cudaGetSymbolAddress((void**)&ctx,  g_ctx);
    cudaGetSymbolAddress((void**)&t1,   g_t1);
    cudaGetSymbolAddress((void**)&X1,   g_X1);
    cudaGetSymbolAddress((void**)&X1R,  g_X1R);
    cudaGetSymbolAddress((void**)&hid,  g_hid);
    cudaGetSymbolAddress((void**)&Wqkv, g_Wqkv);
    cudaGetSymbolAddress((void**)&bqkv, g_bqkv);
    cudaGetSymbolAddress((void**)&WoT,  g_WoT);
    cudaGetSymbolAddress((void**)&W1T,  g_W1T);
    cudaGetSymbolAddress((void**)&W2T,  g_W2T);

    dim3 tblk(32, 8);

    // launches 0-3: QKV weight transposes into packed buffer (+bias pack), Wo
    k_transpose<<<dim3(D_ / 32, D_ / 32), tblk>>>(Wq, Wqkv,            D_, D_, bq, bqkv);
    k_transpose<<<dim3(D_ / 32, D_ / 32), tblk>>>(Wk, Wqkv + (size_t)D_ * D_,     D_, D_, bk, bqkv + D_);
    k_transpose<<<dim3(D_ / 32, D_ / 32), tblk>>>(Wv, Wqkv + (size_t)2 * D_ * D_, D_, D_, bv, bqkv + 2 * D_);
    k_transpose<<<dim3(D_ / 32, D_ / 32), tblk>>>(Wo, WoT, D_, D_, nullptr, nullptr);

    // launch 4: Xp = X + pe (fp32 + rounded copy)
    {
        const size_t n4 = BLD / 4;
        k_add_pe<<<(unsigned)((n4 + 255) / 256), 256>>>(X, pe, Xp, XpR);
    }

    // launch 5 (ncu-profiled): fused QKV projection, N = 3072
    {
        dim3 grid(3 * D_ / 128, M_ROWS / 128);
        k_mmagemm<false, false, true><<<grid, 256>>>(XpR, Wqkv, bqkv,
                                                     q, k, v,
                                                     M_ROWS, 3 * D_, D_);
    }

    // window-3 attention (ctx tf32-rounded at store)
    {
        const int warps  = B_ * L_ * H_;
        const int blocks = warps * 32 / 256;
        k_attn<<<blocks, 256>>>(q, k, v, mask, ctx);
    }

    // output projection
    {
        dim3 grid(D_ / 128, M_ROWS / 128);
        k_mmagemm<false, false, false><<<grid, 256>>>(ctx, WoT, bo,
                                                      t1, nullptr, nullptr,
                                                      M_ROWS, D_, D_);
    }

    // X1 = LN(Xp + t1)  (fp32 + rounded copy)
    k_add_ln<true><<<M_ROWS, 256>>>(Xp, t1, g1, be1, X1, X1R);

    // FFN weight transposes (first needed here)
    k_transpose<<<dim3(FF_ * D_ / 32, D_ / 32), tblk>>>(W1, W1T, D_, FF_ * D_, nullptr, nullptr);
    k_transpose<<<dim3(D_ / 32, FF_ * D_ / 32), tblk>>>(W2, W2T, FF_ * D_, D_, nullptr, nullptr);

    // FFN (hidden rounded in epilogue)
    {
        dim3 grid1(FF_ * D_ / 128, M_ROWS / 128);
        k_mmagemm<true, true, false><<<grid1, 256>>>(X1R, W1T, b1,
                                                     hid, nullptr, nullptr,
                                                     M_ROWS, FF_ * D_, D_);
        dim3 grid2(D_ / 128, M_ROWS / 128);
        k_mmagemm<false, false, false><<<grid2, 256>>>(hid, W2T, b2,
                                                       t1, nullptr, nullptr,
                                                       M_ROWS, D_, FF_ * D_);
    }

    // out = LN(X1 + t1)
    k_add_ln<false><<<M_ROWS, 256>>>(X1, t1, g2, be2, out, nullptr);
}

// round 12
// speedup vs baseline: 1.0791x; 1.0791x over previous
#include <cuda_runtime.h>
#include <stdint.h>

// Problem constants
#define B_  8
#define L_  4096
#define D_  1024
#define H_  16
#define DH_ 64
#define FF_ 4

constexpr int    M_ROWS = B_ * L_;                 // 32768
constexpr size_t BLD    = (size_t)M_ROWS * D_;     // 33,554,432 floats

// -------- scratch (static device globals; no allocations allowed) --------
__device__ float g_Xp  [BLD];                      // X + pe (fp32, residual)
__device__ float g_XpR [BLD];                      // X + pe (tf32-rounded, GEMM A)
__device__ float g_q   [BLD];
__device__ float g_k   [BLD];
__device__ float g_v   [BLD];
__device__ float g_ctx [BLD];                      // attention out (tf32-rounded)
__device__ float g_t1  [BLD];
__device__ float g_X1  [BLD];                      // LN1 out fp32 (residual)
__device__ float g_X1R [BLD];                      // LN1 out tf32-rounded (GEMM A)
__device__ float g_hid [BLD * FF_];                // FFN hidden (tf32-rounded)
// packed transposed+rounded QKV weights: rows 0-1023 Wq^T, 1024-2047 Wk^T, 2048-3071 Wv^T
__device__ float g_Wqkv[(size_t)3 * D_ * D_];
__device__ float g_bqkv[3 * D_];
__device__ float g_WoT [D_ * D_];
__device__ float g_W1T [(size_t)D_ * FF_ * D_];
__device__ float g_W2T [(size_t)FF_ * D_ * D_];

// round fp32 -> tf32 (round-half-up at bit 13); idempotent
__device__ __forceinline__ float f2tf32f(float x) {
    uint32_t u = (__float_as_uint(x) + 0x1000u) & 0xFFFFE000u;
    return __uint_as_float(u);
}

__device__ __forceinline__ void mma_tf32(float* c, const uint32_t* a,
                                         uint32_t b0, uint32_t b1) {
    asm volatile(
        "mma.sync.aligned.m16n8k8.row.col.f32.tf32.tf32.f32 "
        "{%0,%1,%2,%3}, {%4,%5,%6,%7}, {%8,%9}, {%0,%1,%2,%3};\n"
        : "+f"(c[0]), "+f"(c[1]), "+f"(c[2]), "+f"(c[3])
        : "r"(a[0]), "r"(a[1]), "r"(a[2]), "r"(a[3]), "r"(b0), "r"(b1));
}

// =====================================================================
// tf32 mma.sync GEMM, double-buffered static smem (LDG->reg->STS).
// C = A[M,K] @ Bt[N,K]^T + bias; optional ReLU / tf32-round of output.
// SPLIT3: N covers 3 packed outputs; each 128-wide CTA stripe is routed
// to C0/C1/C2 with column offset (stride N/3). bias indexed by packed col.
// CTA tile 128x128, BK=16, 128 threads (4 warps, 2x2), warp tile 64x64.
// SMEM tiles [row][k], pitch 20 floats -> conflict-free fragment loads.
// Inputs must already be tf32-rounded (loader copies raw bits).
// =====================================================================
constexpr int PITCH  = 20;                 // floats per tile row
constexpr int TILE_F = 128 * PITCH;        // 2560 floats per tile

template<bool RELU, bool ROUND, bool SPLIT3>
__global__ __launch_bounds__(128)
void k_mmagemm(const float* __restrict__ A, const float* __restrict__ Bt,
               const float* __restrict__ bias,
               float* __restrict__ C0, float* __restrict__ C1,
               float* __restrict__ C2,
               int M, int N, int K) {
    __shared__ float sm[2][2 * TILE_F];    // [buf][A tile | B tile] = 40960 B

    const int tid  = threadIdx.x;
    const int wid  = tid >> 5;
    const int lane = tid & 31;
    const int ar   = lane >> 2;            // 0..7
    const int ac   = lane & 3;             // 0..3
    const int wm   = (wid & 1) * 64;       // warp m-offset (2x2 warp grid)
    const int wn   = (wid >> 1) * 64;      // warp n-offset

    const int m0 = blockIdx.y * 128;
    const int n0 = blockIdx.x * 128;
    const float* Ag = A  + (size_t)m0 * K;
    const float* Bg = Bt + (size_t)n0 * K;

    // loader mapping: 4 float4 per operand tile per thread per stage
    // id = tid + 128*i -> row = tid>>2 + 32*i, c4 = tid&3 (constant)
    const int rb = tid >> 2;               // row base 0..31
    const int c4 = tid & 3;

    float c[4][8][4];
    #pragma unroll
    for (int mt = 0; mt < 4; mt++)
        #pragma unroll
        for (int nt = 0; nt < 8; nt++)
            #pragma unroll
            for (int i = 0; i < 4; i++) c[mt][nt][i] = 0.f;

    // ---- prologue: stage 0 -> buf 0
    #pragma unroll
    for (int i = 0; i < 4; i++) {
        const int row = rb + 32 * i;
        float4 av = *(const float4*)(Ag + (size_t)row * K + c4 * 4);
        float4 bv = *(const float4*)(Bg + (size_t)row * K + c4 * 4);
        *(float4*)(&sm[0][row * PITCH + c4 * 4])          = av;
        *(float4*)(&sm[0][TILE_F + row * PITCH + c4 * 4]) = bv;
    }
    __syncthreads();

    const int nStages = K >> 4;
    int buf = 0;
    for (int s = 0; s < nStages; s++) {
        const bool has_next = (s + 1 < nStages);
        float4 sa[4], sb[4];
        if (has_next) {
            const int kb = (s + 1) << 4;
            #pragma unroll
            for (int i = 0; i < 4; i++) {
                const int row = rb + 32 * i;
                sa[i] = *(const float4*)(Ag + (size_t)row * K + kb + c4 * 4);
                sb[i] = *(const float4*)(Bg + (size_t)row * K + kb + c4 * 4);
            }
        }

        const float* As = sm[buf];
        const float* Bs = sm[buf] + TILE_F;
        #pragma unroll
        for (int kk = 0; kk < 2; kk++) {
            const int k0 = kk * 8;
            uint32_t afr[4][4];
            #pragma unroll
            for (int mt = 0; mt < 4; mt++) {
                const int mb = wm + mt * 16 + ar;
                afr[mt][0] = __float_as_uint(As[mb * PITCH + k0 + ac]);
                afr[mt][1] = __float_as_uint(As[(mb + 8) * PITCH + k0 + ac]);
                afr[mt][2] = __float_as_uint(As[mb * PITCH + k0 + ac + 4]);
                afr[mt][3] = __float_as_uint(As[(mb + 8) * PITCH + k0 + ac + 4]);
            }
            #pragma unroll
            for (int nt = 0; nt < 8; nt++) {
                const int nb = wn + nt * 8 + ar;
                const uint32_t bb0 = __float_as_uint(Bs[nb * PITCH + k0 + ac]);
                const uint32_t bb1 = __float_as_uint(Bs[nb * PITCH + k0 + ac + 4]);
                #pragma unroll
                for (int mt = 0; mt < 4; mt++)
                    mma_tf32(c[mt][nt], afr[mt], bb0, bb1);
            }
        }

        if (has_next) {
            const int nb2 = buf ^ 1;
            #pragma unroll
            for (int i = 0; i < 4; i++) {
                const int row = rb + 32 * i;
                *(float4*)(&sm[nb2][row * PITCH + c4 * 4])          = sa[i];
                *(float4*)(&sm[nb2][TILE_F + row * PITCH + c4 * 4]) = sb[i];
            }
            __syncthreads();
            buf = nb2;
        }
    }

    // ---- epilogue: route output (SPLIT3), bias (+ReLU) (+round), float2 stores
    float* Cout = C0;
    int    ncol0 = n0;
    int    Nout  = N;
    if (SPLIT3) {
        Nout = N / 3;
        if (n0 >= 2 * Nout)      { Cout = C2; ncol0 = n0 - 2 * Nout; }
        else if (n0 >= Nout)     { Cout = C1; ncol0 = n0 - Nout; }
    }

    #pragma unroll
    for (int nt = 0; nt < 8; nt++) {
        const int coff = wn + nt * 8 + 2 * ac;
        const float2 bb = *(const float2*)(bias + n0 + coff);
        #pragma unroll
        for (int mt = 0; mt < 4; mt++) {
            const int r0 = m0 + wm + mt * 16 + ar;
            float2 o0 = { c[mt][nt][0] + bb.x, c[mt][nt][1] + bb.y };
            float2 o1 = { c[mt][nt][2] + bb.x, c[mt][nt][3] + bb.y };
            if (RELU) {
                o0.x = fmaxf(o0.x, 0.f); o0.y = fmaxf(o0.y, 0.f);
                o1.x = fmaxf(o1.x, 0.f); o1.y = fmaxf(o1.y, 0.f);
            }
            if (ROUND) {
                o0.x = f2tf32f(o0.x); o0.y = f2tf32f(o0.y);
                o1.x = f2tf32f(o1.x); o1.y = f2tf32f(o1.y);
            }
            *(float2*)(Cout + (size_t)r0 * Nout + ncol0 + coff)       = o0;
            *(float2*)(Cout + (size_t)(r0 + 8) * Nout + ncol0 + coff) = o1;
        }
    }
}

// =====================================================================
// weight transpose + tf32 round: Wt[n][k] = round(W[k][n]).
// Optionally packs bias from blocks with blockIdx.y == 0.
// =====================================================================
__global__ void k_transpose(const float* __restrict__ W, float* __restrict__ Wt,
                            int K, int N,
                            const float* __restrict__ bias_src,
                            float* __restrict__ bias_dst) {
    __shared__ float t[32][33];
    const int n0 = blockIdx.x * 32, k0 = blockIdx.y * 32;
    const int tx = threadIdx.x, ty = threadIdx.y;       // (32, 8)
    #pragma unroll
    for (int j = 0; j < 32; j += 8)
        t[ty + j][tx] = W[(size_t)(k0 + ty + j) * N + n0 + tx];
    __syncthreads();
    #pragma unroll
    for (int j = 0; j < 32; j += 8)
        Wt[(size_t)(n0 + ty + j) * K + k0 + tx] = f2tf32f(t[tx][ty + j]);
    if (bias_dst != nullptr && blockIdx.y == 0 && ty == 0)
        bias_dst[n0 + tx] = bias_src[n0 + tx];
}

// =====================================================================
// X + pe -> Xp (fp32) and XpR (tf32-rounded)
// =====================================================================
__global__ void k_add_pe(const float* __restrict__ X,
                         const float* __restrict__ pe,
                         float* __restrict__ outF,
                         float* __restrict__ outR) {
    size_t i = (size_t)blockIdx.x * blockDim.x + threadIdx.x;
    const size_t n4  = BLD / 4;
    const size_t ld4 = (size_t)L_ * D_ / 4;
    if (i >= n4) return;
    const float4 a = ((const float4*)X)[i];
    const float4 p = ((const float4*)pe)[i % ld4];
    float4 o;
    o.x = a.x + p.x; o.y = a.y + p.y; o.z = a.z + p.z; o.w = a.w + p.w;
    ((float4*)outF)[i] = o;
    float4 r = { f2tf32f(o.x), f2tf32f(o.y), f2tf32f(o.z), f2tf32f(o.w) };
    ((float4*)outR)[i] = r;
}

// =====================================================================
// windowed attention (window 3), one warp per (b,l,h); tf32-rounded out
// =====================================================================
__global__ void k_attn(const float* __restrict__ q, const float* __restrict__ k,
                       const float* __restrict__ v,
                       const uint8_t* __restrict__ mask,
                       float* __restrict__ ctx) {
    const int gw   = (int)(((size_t)blockIdx.x * blockDim.x + threadIdx.x) >> 5);
    const int lane = threadIdx.x & 31;
    if (gw >= B_ * L_ * H_) return;
    const int h  = gw % H_;
    const int bl = gw / H_;
    const int l  = bl % L_;
    const int b  = bl / L_;

    const float* qp = q + (size_t)bl * D_ + h * DH_;
    const float  q0 = qp[lane];
    const float  q1 = qp[lane + 32];

    float s[3], v0[3], v1[3];
    bool  allow[3];
    #pragma unroll
    for (int w = 0; w < 3; w++) {
        const int j     = l + w - 1;
        const bool vald = (j >= 0) && (j < L_);
        const int jc    = min(max(j, 0), L_ - 1);
        const size_t kr = ((size_t)b * L_ + jc) * D_ + h * DH_;
        float p = q0 * k[kr + lane] + q1 * k[kr + lane + 32];
        #pragma unroll
        for (int o = 16; o > 0; o >>= 1) p += __shfl_xor_sync(0xffffffffu, p, o);
        s[w]     = p * 0.125f;
        allow[w] = vald && (mask[(size_t)b * L_ + jc] == 0);
        v0[w]    = v[kr + lane];
        v1[w]    = v[kr + lane + 32];
    }

    float sw[3], m = -1e30f;
    #pragma unroll
    for (int w = 0; w < 3; w++) { sw[w] = allow[w] ? s[w] : -1e30f; m = fmaxf(m, sw[w]); }
    float e[3], sum = 0.f;
    #pragma unroll
    for (int w = 0; w < 3; w++) { e[w] = expf(sw[w] - m); sum += e[w]; }
    const float inv = 1.f / sum;
    float o0 = 0.f, o1 = 0.f;
    #pragma unroll
    for (int w = 0; w < 3; w++) {
        const float a = e[w] * inv;
        o0 = fmaf(a, v0[w], o0);
        o1 = fmaf(a, v1[w], o1);
    }
    float* cp = ctx + (size_t)bl * D_ + h * DH_;
    cp[lane]      = f2tf32f(o0);
    cp[lane + 32] = f2tf32f(o1);
}

// =====================================================================
// out = layernorm(A + R) * g + beta ; optional rounded second output
// =====================================================================
__device__ __forceinline__ float block_sum(float val, float* sbuf) {
    const int lane = threadIdx.x & 31, wid = threadIdx.x >> 5;
    #pragma unroll
    for (int o = 16; o > 0; o >>= 1) val += __shfl_xor_sync(0xffffffffu, val, o);
    if (lane == 0) sbuf[wid] = val;
    __syncthreads();
    if (wid == 0) {
        float vv = (lane < 8) ? sbuf[lane] : 0.f;
        #pragma unroll
        for (int o = 4; o > 0; o >>= 1) vv += __shfl_xor_sync(0xffffffffu, vv, o);
        if (lane == 0) sbuf[0] = vv;
    }
    __syncthreads();
    const float r = sbuf[0];
    __syncthreads();
    return r;
}

template<bool DUAL>
__global__ __launch_bounds__(256)
void k_add_ln(const float* __restrict__ A, const float* __restrict__ R,
              const float* __restrict__ g, const float* __restrict__ beta,
              float* __restrict__ out, float* __restrict__ outR) {
    __shared__ float sbuf[8];
    const int row = blockIdx.x;
    const int tid = threadIdx.x;
    const size_t base = (size_t)row * D_;

    const float4 a = ((const float4*)(A + base))[tid];
    const float4 r = ((const float4*)(R + base))[tid];
    float x[4] = { a.x + r.x, a.y + r.y, a.z + r.z, a.w + r.w };

    float ps = x[0] + x[1] + x[2] + x[3];
    const float mean = block_sum(ps, sbuf) * (1.f / D_);

    float pv = 0.f;
    #pragma unroll
    for (int i = 0; i < 4; i++) { const float d = x[i] - mean; pv += d * d; }
    const float var = block_sum(pv, sbuf) * (1.f / D_);
    const float rstd = rsqrtf(var + 1e-5f);

    const float4 gg = ((const float4*)g)[tid];
    const float4 bb = ((const float4*)beta)[tid];
    float4 o;
    o.x = (x[0] - mean) * rstd * gg.x + bb.x;
    o.y = (x[1] - mean) * rstd * gg.y + bb.y;
    o.z = (x[2] - mean) * rstd * gg.z + bb.z;
    o.w = (x[3] - mean) * rstd * gg.w + bb.w;
    ((float4*)(out + base))[tid] = o;
    if (DUAL) {
        float4 rr = { f2tf32f(o.x), f2tf32f(o.y), f2tf32f(o.z), f2tf32f(o.w) };
        ((float4*)(outR + base))[tid] = rr;
    }
}

// =====================================================================
// launch
// =====================================================================
extern "C" void kernel_launch(void* const* d_in, const int* in_sizes, int n_in,
                              void* d_out, int out_size) {
    const float*   X    = (const float*)d_in[0];
    const uint8_t* mask = (const uint8_t*)d_in[1];
    const float*   pe   = (const float*)d_in[2];
    const float*   Wq   = (const float*)d_in[3];
    const float*   Wk   = (const float*)d_in[4];
    const float*   Wv   = (const float*)d_in[5];
    const float*   bq   = (const float*)d_in[6];
    const float*   bk   = (const float*)d_in[7];
    const float*   bv   = (const float*)d_in[8];
    const float*   Wo   = (const float*)d_in[9];
    const float*   bo   = (const float*)d_in[10];
    const float*   g1   = (const float*)d_in[11];
    const float*   be1  = (const float*)d_in[12];
    const float*   W1   = (const float*)d_in[13];
    const float*   b1   = (const float*)d_in[14];
    const float*   W2   = (const float*)d_in[15];
    const float*   b2   = (const float*)d_in[16];
    const float*   g2   = (const float*)d_in[17];
    const float*   be2  = (const float*)d_in[18];
    float*         out  = (float*)d_out;

    float *Xp, *XpR, *q, *k, *v, *ctx, *t1, *X1, *X1R, *hid;
    float *Wqkv, *bqkv, *WoT, *W1T, *W2T;
    cudaGetSymbolAddress((void**)&Xp,   g_Xp);
    cudaGetSymbolAddress((void**)&XpR,  g_XpR);
    cudaGetSymbolAddress((void**)&q,    g_q);
    cudaGetSymbolAddress((void**)&k,    g_k);
    cudaGetSymbolAddress((void**)&v,    g_v);
    cudaGetSymbolAddress((void**)&ctx,  g_ctx);
    cudaGetSymbolAddress((void**)&t1,   g_t1);
    cudaGetSymbolAddress((void**)&X1,   g_X1);
    cudaGetSymbolAddress((void**)&X1R,  g_X1R);
    cudaGetSymbolAddress((void**)&hid,  g_hid);
    cudaGetSymbolAddress((void**)&Wqkv, g_Wqkv);
    cudaGetSymbolAddress((void**)&bqkv, g_bqkv);
    cudaGetSymbolAddress((void**)&WoT,  g_WoT);
    cudaGetSymbolAddress((void**)&W1T,  g_W1T);
    cudaGetSymbolAddress((void**)&W2T,  g_W2T);

    dim3 tblk(32, 8);

    // QKV weight transposes into packed buffer (+bias pack), Wo
    k_transpose<<<dim3(D_ / 32, D_ / 32), tblk>>>(Wq, Wqkv,            D_, D_, bq, bqkv);
    k_transpose<<<dim3(D_ / 32, D_ / 32), tblk>>>(Wk, Wqkv + (size_t)D_ * D_,     D_, D_, bk, bqkv + D_);
    k_transpose<<<dim3(D_ / 32, D_ / 32), tblk>>>(Wv, Wqkv + (size_t)2 * D_ * D_, D_, D_, bv, bqkv + 2 * D_);
    k_transpose<<<dim3(D_ / 32, D_ / 32), tblk>>>(Wo, WoT, D_, D_, nullptr, nullptr);

    // Xp = X + pe (fp32 + rounded copy)
    {
        const size_t n4 = BLD / 4;
        k_add_pe<<<(unsigned)((n4 + 255) / 256), 256>>>(X, pe, Xp, XpR);
    }

    // fused QKV projection, N = 3072
    {
        dim3 grid(3 * D_ / 128, M_ROWS / 128);
        k_mmagemm<false, false, true><<<grid, 128>>>(XpR, Wqkv, bqkv,
                                                     q, k, v,
                                                     M_ROWS, 3 * D_, D_);
    }

    // window-3 attention (ctx tf32-rounded at store)
    {
        const int warps  = B_ * L_ * H_;
        const int blocks = warps * 32 / 256;
        k_attn<<<blocks, 256>>>(q, k, v, mask, ctx);
    }

    // output projection
    {
        dim3 grid(D_ / 128, M_ROWS / 128);
        k_mmagemm<false, false, false><<<grid, 128>>>(ctx, WoT, bo,
                                                      t1, nullptr, nullptr,
                                                      M_ROWS, D_, D_);
    }

    // X1 = LN(Xp + t1)  (fp32 + rounded copy)
    k_add_ln<true><<<M_ROWS, 256>>>(Xp, t1, g1, be1, X1, X1R);

    // FFN weight transposes
    k_transpose<<<dim3(FF_ * D_ / 32, D_ / 32), tblk>>>(W1, W1T, D_, FF_ * D_, nullptr, nullptr);
    k_transpose<<<dim3(D_ / 32, FF_ * D_ / 32), tblk>>>(W2, W2T, FF_ * D_, D_, nullptr, nullptr);

    // FFN (hidden rounded in epilogue)
    {
        dim3 grid1(FF_ * D_ / 128, M_ROWS / 128);
        k_mmagemm<true, true, false><<<grid1, 128>>>(X1R, W1T, b1,
                                                     hid, nullptr, nullptr,
                                                     M_ROWS, FF_ * D_, D_);
        dim3 grid2(D_ / 128, M_ROWS / 128);
        k_mmagemm<false, false, false><<<grid2, 128>>>(hid, W2T, b2,
                                                       t1, nullptr, nullptr,
                                                       M_ROWS, D_, FF_ * D_);
    }

    // out = LN(X1 + t1)
    k_add_ln<false><<<M_ROWS, 256>>>(X1, t1, g2, be2, out, nullptr);
}